// round 7
// baseline (speedup 1.0000x reference)
#include <cuda_runtime.h>
#include <math.h>
#include <stdint.h>

// ---------------------------------------------------------------------------
// S4DTransitionModel — tf32 tensor-core fused heads, fragment-native epilogues,
// double-buffered weight staging (1 barrier per 32-k tile).
//   B=8192, LATENT=256, CD=128, U=32, N_Y=50, H=256, SEL_IN=289
// Pipeline:
//   sel_gemm_kernel x3  : x=concat(zt,ut,dt) -> h0 -> h1 -> hz   (fp32, BN+ReLU)
//   fused_heads_kernel  : per 32-row batch tile, stream ALL head weights
//                         through SMEM in 128-row chunks; chunk GEMM on
//                         mma.sync.m16n8k8.tf32 (register-prefetched weights);
//                         every epilogue consumes mma fragments directly.
// Fragment map (warp ty, lane = gid*4+tig):
//   c[nt][0]=D[m0][n] c[nt][1]=D[m0][n+1] c[nt][2]=D[m0+8][n] c[nt][3]=D[m0+8][n+1]
//   m0 = (ty&1)*16 + gid,  n = (ty>>1)*32 + nt*8 + tig*2
// ---------------------------------------------------------------------------

#define BATCH   8192
#define LATENT  256
#define CDIM    128
#define UDIM    32
#define NY      50
#define HID     256
#define SELIN   289

#define BROWS   32            // batch rows per block

// scratch (static device arrays — no allocation)
__device__ float g_buf0[BATCH * HID];
__device__ float g_buf1[BATCH * HID];
__device__ float g_hz  [BATCH * LATENT];

// ---------------------------------------------------------------------------
// Selector GEMM (fp32): C[M,256] = act(A[M,K] @ W[256,K]^T + b)
// flags: bit0 = input is concat(zt,ut,dt) (K=289), bit1 = BatchNorm+ReLU
// ---------------------------------------------------------------------------
__global__ __launch_bounds__(256) void sel_gemm_kernel(
    const float* __restrict__ A,
    const float* __restrict__ zt,
    const float* __restrict__ ut,
    const float* __restrict__ dtv,
    const float* __restrict__ W,
    const float* __restrict__ bias,
    const float* __restrict__ gam,
    const float* __restrict__ bet,
    float* __restrict__ C,
    int K, int flags)
{
    __shared__ float As[16][65];
    __shared__ float Bs[16][65];

    const int t  = threadIdx.x;
    const int tx = t & 15;
    const int ty = t >> 4;
    const int m0 = blockIdx.x * 64;
    const int n0 = blockIdx.y * 64;

    float acc[4][4];
#pragma unroll
    for (int i = 0; i < 4; i++)
#pragma unroll
        for (int j = 0; j < 4; j++) acc[i][j] = 0.f;

    const int ktiles = (K + 15) >> 4;
    for (int kt = 0; kt < ktiles; kt++) {
        const int k0 = kt * 16;
        __syncthreads();
#pragma unroll
        for (int i = 0; i < 4; i++) {
            int idx = t + 256 * i;
            int kk = idx & 15;
            int m  = idx >> 4;     // 0..63
            int k  = k0 + kk;
            int b  = m0 + m;
            float av;
            if (flags & 1) {
                av = (k < 256) ? zt[(size_t)b * 256 + k]
                   : (k < 288) ? ut[(size_t)b * 32 + (k - 256)]
                   : (k == 288) ? dtv[b] : 0.f;
            } else {
                av = (k < K) ? A[(size_t)b * K + k] : 0.f;
            }
            As[kk][m] = av;
            Bs[kk][m] = (k < K) ? W[(size_t)(n0 + m) * K + k] : 0.f;
        }
        __syncthreads();
#pragma unroll
        for (int kk = 0; kk < 16; kk++) {
            float a[4], bb[4];
#pragma unroll
            for (int i = 0; i < 4; i++) a[i]  = As[kk][ty * 4 + i];
#pragma unroll
            for (int j = 0; j < 4; j++) bb[j] = Bs[kk][tx * 4 + j];
#pragma unroll
            for (int i = 0; i < 4; i++)
#pragma unroll
                for (int j = 0; j < 4; j++)
                    acc[i][j] = fmaf(a[i], bb[j], acc[i][j]);
        }
    }

    const float RS = rsqrtf(1.0f + 1e-5f);   // BN eval: mean=0, var=1
#pragma unroll
    for (int i = 0; i < 4; i++) {
#pragma unroll
        for (int j = 0; j < 4; j++) {
            int row = m0 + ty * 4 + i;
            int col = n0 + tx * 4 + j;
            float v = acc[i][j] + bias[col];
            if (flags & 2) {
                v = fmaf(gam[col], v * RS, bet[col]);
                v = fmaxf(v, 0.f);
            }
            C[(size_t)row * 256 + col] = v;
        }
    }
}

// ---------------------------------------------------------------------------
// tf32 helpers
// ---------------------------------------------------------------------------
__device__ __forceinline__ uint32_t tf32_of(float x) {
    uint32_t u;
    asm("cvt.rna.tf32.f32 %0, %1;" : "=r"(u) : "f"(x));
    return u;
}

__device__ __forceinline__ void mma_tf32(
    float c[4], uint32_t a0, uint32_t a1, uint32_t a2, uint32_t a3,
    uint32_t b0, uint32_t b1)
{
    asm volatile(
        "mma.sync.aligned.m16n8k8.row.col.f32.tf32.tf32.f32 "
        "{%0,%1,%2,%3}, {%4,%5,%6,%7}, {%8,%9}, {%0,%1,%2,%3};"
        : "+f"(c[0]), "+f"(c[1]), "+f"(c[2]), "+f"(c[3])
        : "r"(a0), "r"(a1), "r"(a2), "r"(a3), "r"(b0), "r"(b1));
}

#define WBUF 4224   // floats per sW buffer (16 p-rows * 264)

// ---------------------------------------------------------------------------
// Chunk GEMM on tensor cores; returns raw fragments c[4][4].
//   - sHz: [32 rows][264] tf32-rounded fp32, paired-k layout:
//       word(row, k) = row*264 + ((k>>3)*4 + (k&3))*2 + ((k&7)>>2)
//   - sW : two buffers of WBUF floats; per 32-k tile,
//       word(kk, r) = p*264 + r*2 + hi, p=(kk>>3)*4+(kk&3), hi=(kk&7)>>2.
// Double-buffered: stage buf[kt&1] -> ONE barrier -> mma from buf[kt&1].
// The barrier at tile kt also separates all warps' mma reads of buf[(kt-1)&1]
// (tile kt-1) from any warp's stage writes at tile kt+1 (same buffer).
// Register prefetch: next k-tile's 16 weights fetched right after STS.
// ---------------------------------------------------------------------------
__device__ __forceinline__ void gemm_chunk(
    const float* __restrict__ Wg, int r0, int rows,
    const float* __restrict__ sHz, float* __restrict__ sW,
    int tx, int ty, float c[4][4])
{
    const int t   = ty * 32 + tx;
    const int r   = t >> 1;          // weight row within chunk: 0..127
    const int kh  = (t & 1) * 16;    // k-half within 32-k tile
    const int gid = tx >> 2;
    const int tig = tx & 3;
    const int mw  = (ty & 1) * 16;
    const int nw  = (ty >> 1) * 32;

#pragma unroll
    for (int nt = 0; nt < 4; nt++)
#pragma unroll
        for (int j = 0; j < 4; j++) c[nt][j] = 0.f;

    const float* abase = sHz + (mw + gid) * 264 + tig * 2;
    const bool valid = (r < rows);
    const float4* wrow = (const float4*)(Wg + (size_t)(r0 + r) * 256 + kh);

    // prefetch tile kt=0
    float4 v0, v1, v2, v3;
    if (valid) {
        v0 = wrow[0]; v1 = wrow[1]; v2 = wrow[2]; v3 = wrow[3];
    } else {
        v0 = make_float4(0.f, 0.f, 0.f, 0.f);
        v1 = v0; v2 = v0; v3 = v0;
    }

#pragma unroll 2
    for (int kt = 0; kt < 8; kt++) {
        float* buf = sW + (kt & 1) * WBUF;
        float vv[16];
        vv[0]=v0.x; vv[1]=v0.y; vv[2]=v0.z; vv[3]=v0.w;
        vv[4]=v1.x; vv[5]=v1.y; vv[6]=v1.z; vv[7]=v1.w;
        vv[8]=v2.x; vv[9]=v2.y; vv[10]=v2.z; vv[11]=v2.w;
        vv[12]=v3.x; vv[13]=v3.y; vv[14]=v3.z; vv[15]=v3.w;
#pragma unroll
        for (int j = 0; j < 16; j++) {
            int kk = kh + j;
            int p  = ((kk >> 3) << 2) + (kk & 3);
            int hi = (kk & 7) >> 2;
            buf[p * 264 + r * 2 + hi] = __uint_as_float(tf32_of(vv[j]));
        }
        if (kt < 7 && valid) {     // prefetch next tile (overlaps barrier+mma)
            const float4* src = wrow + (kt + 1) * 8;
            v0 = src[0]; v1 = src[1]; v2 = src[2]; v3 = src[3];
        }
        __syncthreads();           // staging of buf[kt&1] visible to all

        const float* ab = abase + kt * 32;
#pragma unroll
        for (int ks = 0; ks < 4; ks++) {
            float2 al = *(const float2*)(ab + ks * 8);
            float2 ah = *(const float2*)(ab + ks * 8 + 8 * 264);
            uint32_t a0 = __float_as_uint(al.x);
            uint32_t a1 = __float_as_uint(ah.x);
            uint32_t a2 = __float_as_uint(al.y);
            uint32_t a3 = __float_as_uint(ah.y);
            const float* bb = buf + (ks * 4 + tig) * 264 + (nw + gid) * 2;
#pragma unroll
            for (int nt = 0; nt < 4; nt++) {
                float2 bp = *(const float2*)(bb + nt * 16);
                mma_tf32(c[nt], a0, a1, a2, a3,
                         __float_as_uint(bp.x), __float_as_uint(bp.y));
            }
        }
    }
}

// reduce a value over the 4 tig lanes (lane = gid*4 + tig)
__device__ __forceinline__ float red4(float s) {
    s += __shfl_xor_sync(0xffffffffu, s, 1);
    s += __shfl_xor_sync(0xffffffffu, s, 2);
    return s;
}

// Bt chunk: warp quarter = one c index; contract over u, += into sZ[m][c].
__device__ __forceinline__ void bt_epilogue(
    const float c[4][4], const float* __restrict__ bias, int r0,
    const float* __restrict__ sU, float* __restrict__ sZ, int tx, int ty)
{
    const int gid = tx >> 2, tig = tx & 3;
    const int m0r = (ty & 1) * 16 + gid;
    const int nw  = (ty >> 1) * 32;
    const int cidx = (r0 >> 5) + (ty >> 1);
    float s0 = 0.f, s1 = 0.f;
#pragma unroll
    for (int nt = 0; nt < 4; nt++)
#pragma unroll
        for (int e = 0; e < 2; e++) {
            int uu = nt * 8 + tig * 2 + e;           // ncol & 31
            float vb = __ldg(bias + r0 + nw + uu);
            s0 = fmaf(c[nt][e]     + vb, sU[m0r * 32 + uu],       s0);
            s1 = fmaf(c[nt][2 + e] + vb, sU[(m0r + 8) * 32 + uu], s1);
        }
    s0 = red4(s0); s1 = red4(s1);
    if (tig == 0) {
        sZ[m0r * 128 + cidx]       += s0;
        sZ[(m0r + 8) * 128 + cidx] += s1;
    }
}

// Ct chunk (one y per chunk): contract over this warp's 32 c's with sZ,
// combine quarters via smem atomicAdd.
__device__ __forceinline__ void ct_epilogue(
    const float c[4][4], const float* __restrict__ bias, int y,
    const float* __restrict__ sZ, float sign, float* __restrict__ sYt,
    int tx, int ty)
{
    const int gid = tx >> 2, tig = tx & 3;
    const int m0r = (ty & 1) * 16 + gid;
    const int nw  = (ty >> 1) * 32;
    float s0 = 0.f, s1 = 0.f;
#pragma unroll
    for (int nt = 0; nt < 4; nt++)
#pragma unroll
        for (int e = 0; e < 2; e++) {
            int colg = nw + nt * 8 + tig * 2 + e;    // c index 0..127
            float vb = __ldg(bias + y * 128 + colg);
            s0 = fmaf(c[nt][e]     + vb, sZ[m0r * 128 + colg],       s0);
            s1 = fmaf(c[nt][2 + e] + vb, sZ[(m0r + 8) * 128 + colg], s1);
        }
    s0 = red4(s0); s1 = red4(s1);
    if (tig == 0) {
        atomicAdd(&sYt[m0r * 64 + y],       sign * s0);
        atomicAdd(&sYt[(m0r + 8) * 64 + y], sign * s1);
    }
}

// Dt chunk: warp quarter = one y; contract over u, += into sYt[m][y].
__device__ __forceinline__ void dt_epilogue(
    const float c[4][4], const float* __restrict__ bias, int r0, int rows,
    const float* __restrict__ sU, float* __restrict__ sYt, int tx, int ty)
{
    const int nw = (ty >> 1) * 32;
    if (nw >= rows) return;                          // last chunk: 64 rows
    const int gid = tx >> 2, tig = tx & 3;
    const int m0r = (ty & 1) * 16 + gid;
    const int y   = (r0 >> 5) + (ty >> 1);           // <= 49
    float s0 = 0.f, s1 = 0.f;
#pragma unroll
    for (int nt = 0; nt < 4; nt++)
#pragma unroll
        for (int e = 0; e < 2; e++) {
            int uu = nt * 8 + tig * 2 + e;
            float vb = __ldg(bias + r0 + nw + uu);
            s0 = fmaf(c[nt][e]     + vb, sU[m0r * 32 + uu],       s0);
            s1 = fmaf(c[nt][2 + e] + vb, sU[(m0r + 8) * 32 + uu], s1);
        }
    s0 = red4(s0); s1 = red4(s1);
    if (tig == 0) {
        sYt[m0r * 64 + y]       += s0;
        sYt[(m0r + 8) * 64 + y] += s1;
    }
}

// SMEM floats: sHz 8448 | sW 2*4224 | sU 1024 | sZnr 4096 | sZni 4096 | sYt 2048
#define SMEM_FLOATS 28160     // 112640 bytes -> 2 blocks/SM (225280 B / 228 KB)

__global__ __launch_bounds__(256, 2) void fused_heads_kernel(
    const float* __restrict__ zt,   const float* __restrict__ dtv,
    const float* __restrict__ ut,
    const float* __restrict__ aw,   const float* __restrict__ ab,
    const float* __restrict__ ow,   const float* __restrict__ ob,
    const float* __restrict__ btrw, const float* __restrict__ btrb,
    const float* __restrict__ btiw, const float* __restrict__ btib,
    const float* __restrict__ ctrw, const float* __restrict__ ctrb,
    const float* __restrict__ ctiw, const float* __restrict__ ctib,
    const float* __restrict__ dtww, const float* __restrict__ dtwb,
    float* __restrict__ out)
{
    extern __shared__ float sm[];
    float* sHz  = sm;             // [32][264] tf32 paired-k
    float* sW   = sm + 8448;      // [2][4224] weight tile double buffer
    float* sU   = sm + 16896;     // [32][32]  ut*dt
    float* sZnr = sm + 17920;     // [32][128]
    float* sZni = sm + 22016;     // [32][128]
    float* sYt  = sm + 26112;     // [32][64]

    const int t  = threadIdx.x;
    const int tx = t & 31;
    const int ty = t >> 5;
    const int b0 = blockIdx.x * BROWS;

    const int gid = tx >> 2, tig = tx & 3;
    const int m0r = (ty & 1) * 16 + gid;
    const int nw  = (ty >> 1) * 32;

    // phase 0: stage per-tile state (covered by first barrier in gemm_chunk)
    for (int idx = t; idx < BROWS * 256; idx += 256) {
        int row = idx >> 8, k = idx & 255;
        int p  = ((k >> 3) << 2) + (k & 3);
        int hi = (k & 7) >> 2;
        sHz[row * 264 + p * 2 + hi] =
            __uint_as_float(tf32_of(g_hz[(size_t)b0 * 256 + idx]));
    }
    for (int idx = t; idx < BROWS * 32; idx += 256) {
        int br = idx >> 5;
        sU[idx] = ut[(size_t)(b0 + br) * 32 + (idx & 31)] * dtv[b0 + br];
    }
    for (int idx = t; idx < BROWS * 64; idx += 256) sYt[idx] = 0.f;

    float c[4][4], ea[4][4];

    // alpha -> exp(-softplus(v)) == sigmoid(-v); fragment-native
    gemm_chunk(aw, 0, 128, sHz, sW, tx, ty, c);
#pragma unroll
    for (int nt = 0; nt < 4; nt++)
#pragma unroll
        for (int j = 0; j < 4; j++) {
            int colg = nw + nt * 8 + tig * 2 + (j & 1);
            float v = c[nt][j] + __ldg(ab + colg);
            ea[nt][j] = 1.0f / (1.0f + expf(v));
        }

    // omega -> Lam = ea*(cos,sin); init z_next = Lam * z; direct stores
    gemm_chunk(ow, 0, 128, sHz, sW, tx, ty, c);
#pragma unroll
    for (int nt = 0; nt < 4; nt++)
#pragma unroll
        for (int j = 0; j < 4; j++) {
            int colg = nw + nt * 8 + tig * 2 + (j & 1);
            int m    = m0r + ((j >> 1) ? 8 : 0);
            float v = c[nt][j] + __ldg(ob + colg);
            float sn, cs;
            sincosf(v, &sn, &cs);
            float lr = ea[nt][j] * cs;
            float li = ea[nt][j] * sn;
            int b = b0 + m;
            float zr = __ldg(zt + (size_t)b * 256 + colg);
            float zi = __ldg(zt + (size_t)b * 256 + 128 + colg);
            sZnr[m * 128 + colg] = lr * zr - li * zi;
            sZni[m * 128 + colg] = lr * zi + li * zr;
        }

    // Bt real / imag: 32 chunks each (4096 rows / 128)
    for (int ch = 0; ch < 32; ch++) {
        gemm_chunk(btrw, ch * 128, 128, sHz, sW, tx, ty, c);
        bt_epilogue(c, btrb, ch * 128, sU, sZnr, tx, ty);
    }
    for (int ch = 0; ch < 32; ch++) {
        gemm_chunk(btiw, ch * 128, 128, sHz, sW, tx, ty, c);
        bt_epilogue(c, btib, ch * 128, sU, sZni, tx, ty);
    }

    // Ct real / imag: 50 chunks each (one y per 128-row chunk)
    for (int y = 0; y < NY; y++) {
        gemm_chunk(ctrw, y * 128, 128, sHz, sW, tx, ty, c);
        ct_epilogue(c, ctrb, y, sZnr, 1.f, sYt, tx, ty);
    }
    for (int y = 0; y < NY; y++) {
        gemm_chunk(ctiw, y * 128, 128, sHz, sW, tx, ty, c);
        ct_epilogue(c, ctib, y, sZni, -1.f, sYt, tx, ty);
    }

    // Dt: 1600 rows = 12 full chunks + 64
    for (int ch = 0; ch < 13; ch++) {
        int rows = (ch == 12) ? 64 : 128;
        gemm_chunk(dtww, ch * 128, rows, sHz, sW, tx, ty, c);
        dt_epilogue(c, dtwb, ch * 128, rows, sU, sYt, tx, ty);
    }

    __syncthreads();

    // outputs: z_next_real [B,256] then yt [B,50]
    for (int idx = t; idx < BROWS * 256; idx += 256) {
        int br = idx >> 8;
        int j  = idx & 255;
        float v = (j < 128) ? sZnr[br * 128 + j] : sZni[br * 128 + j - 128];
        out[(size_t)(b0 + br) * 256 + j] = v;
    }
    for (int idx = t; idx < BROWS * NY; idx += 256) {
        int br = idx / NY;
        int y  = idx % NY;
        out[(size_t)BATCH * 256 + (size_t)(b0 + br) * NY + y] = sYt[br * 64 + y];
    }
}

// ---------------------------------------------------------------------------
extern "C" void kernel_launch(void* const* d_in, const int* in_sizes, int n_in,
                              void* d_out, int out_size)
{
    const float* zt   = (const float*)d_in[0];
    const float* dtv  = (const float*)d_in[1];
    const float* ut   = (const float*)d_in[2];
    const float* sw0  = (const float*)d_in[3];
    const float* sb0  = (const float*)d_in[4];
    const float* sg0  = (const float*)d_in[5];
    const float* sbe0 = (const float*)d_in[6];
    const float* sw1  = (const float*)d_in[7];
    const float* sb1  = (const float*)d_in[8];
    const float* sg1  = (const float*)d_in[9];
    const float* sbe1 = (const float*)d_in[10];
    const float* sw2  = (const float*)d_in[11];
    const float* sb2  = (const float*)d_in[12];
    const float* aw   = (const float*)d_in[13];
    const float* ab   = (const float*)d_in[14];
    const float* ow   = (const float*)d_in[15];
    const float* ob   = (const float*)d_in[16];
    const float* btrw = (const float*)d_in[17];
    const float* btrb = (const float*)d_in[18];
    const float* btiw = (const float*)d_in[19];
    const float* btib = (const float*)d_in[20];
    const float* ctrw = (const float*)d_in[21];
    const float* ctrb = (const float*)d_in[22];
    const float* ctiw = (const float*)d_in[23];
    const float* ctib = (const float*)d_in[24];
    const float* dtww = (const float*)d_in[25];
    const float* dtwb = (const float*)d_in[26];

    float *p0, *p1, *phz;
    cudaGetSymbolAddress((void**)&p0,  g_buf0);
    cudaGetSymbolAddress((void**)&p1,  g_buf1);
    cudaGetSymbolAddress((void**)&phz, g_hz);

    dim3 gsel(BATCH / 64, 256 / 64);
    // layer0: concat input, BN+ReLU
    sel_gemm_kernel<<<gsel, 256>>>(nullptr, zt, ut, dtv,
                                   sw0, sb0, sg0, sbe0, p0, SELIN, 3);
    // layer1: BN+ReLU
    sel_gemm_kernel<<<gsel, 256>>>(p0, nullptr, nullptr, nullptr,
                                   sw1, sb1, sg1, sbe1, p1, 256, 2);
    // layer2: plain linear -> hz
    sel_gemm_kernel<<<gsel, 256>>>(p1, nullptr, nullptr, nullptr,
                                   sw2, sb2, nullptr, nullptr, phz, 256, 0);

    const int smem_bytes = SMEM_FLOATS * (int)sizeof(float);  // 112640
    cudaFuncSetAttribute(fused_heads_kernel,
                         cudaFuncAttributeMaxDynamicSharedMemorySize, smem_bytes);
    fused_heads_kernel<<<BATCH / BROWS, 256, smem_bytes>>>(
        zt, dtv, ut,
        aw, ab, ow, ob,
        btrw, btrb, btiw, btib,
        ctrw, ctrb, ctiw, ctib,
        dtww, dtwb,
        (float*)d_out);
}

// round 9
// speedup vs baseline: 1.0807x; 1.0807x over previous
#include <cuda_runtime.h>
#include <math.h>
#include <stdint.h>

// ---------------------------------------------------------------------------
// S4DTransitionModel — tf32 tensor-core fused heads, fragment-native epilogues,
// double-buffered weight staging, conflict-free STS (hi ^ p>>3 parity trick).
//   B=8192, LATENT=256, CD=128, U=32, N_Y=50, H=256, SEL_IN=289
// ---------------------------------------------------------------------------

#define BATCH   8192
#define LATENT  256
#define CDIM    128
#define UDIM    32
#define NY      50
#define HID     256
#define SELIN   289

#define BROWS   32            // batch rows per block

// scratch (static device arrays — no allocation)
__device__ float g_buf0[BATCH * HID];
__device__ float g_buf1[BATCH * HID];
__device__ float g_hz  [BATCH * LATENT];

// ---------------------------------------------------------------------------
// Selector GEMM (fp32): C[M,256] = act(A[M,K] @ W[256,K]^T + b)
// flags: bit0 = input is concat(zt,ut,dt) (K=289), bit1 = BatchNorm+ReLU
// ---------------------------------------------------------------------------
__global__ __launch_bounds__(256) void sel_gemm_kernel(
    const float* __restrict__ A,
    const float* __restrict__ zt,
    const float* __restrict__ ut,
    const float* __restrict__ dtv,
    const float* __restrict__ W,
    const float* __restrict__ bias,
    const float* __restrict__ gam,
    const float* __restrict__ bet,
    float* __restrict__ C,
    int K, int flags)
{
    __shared__ float As[16][65];
    __shared__ float Bs[16][65];

    const int t  = threadIdx.x;
    const int tx = t & 15;
    const int ty = t >> 4;
    const int m0 = blockIdx.x * 64;
    const int n0 = blockIdx.y * 64;

    float acc[4][4];
#pragma unroll
    for (int i = 0; i < 4; i++)
#pragma unroll
        for (int j = 0; j < 4; j++) acc[i][j] = 0.f;

    const int ktiles = (K + 15) >> 4;
    for (int kt = 0; kt < ktiles; kt++) {
        const int k0 = kt * 16;
        __syncthreads();
#pragma unroll
        for (int i = 0; i < 4; i++) {
            int idx = t + 256 * i;
            int kk = idx & 15;
            int m  = idx >> 4;     // 0..63
            int k  = k0 + kk;
            int b  = m0 + m;
            float av;
            if (flags & 1) {
                av = (k < 256) ? zt[(size_t)b * 256 + k]
                   : (k < 288) ? ut[(size_t)b * 32 + (k - 256)]
                   : (k == 288) ? dtv[b] : 0.f;
            } else {
                av = (k < K) ? A[(size_t)b * K + k] : 0.f;
            }
            As[kk][m] = av;
            Bs[kk][m] = (k < K) ? W[(size_t)(n0 + m) * K + k] : 0.f;
        }
        __syncthreads();
#pragma unroll
        for (int kk = 0; kk < 16; kk++) {
            float a[4], bb[4];
#pragma unroll
            for (int i = 0; i < 4; i++) a[i]  = As[kk][ty * 4 + i];
#pragma unroll
            for (int j = 0; j < 4; j++) bb[j] = Bs[kk][tx * 4 + j];
#pragma unroll
            for (int i = 0; i < 4; i++)
#pragma unroll
                for (int j = 0; j < 4; j++)
                    acc[i][j] = fmaf(a[i], bb[j], acc[i][j]);
        }
    }

    const float RS = rsqrtf(1.0f + 1e-5f);   // BN eval: mean=0, var=1
#pragma unroll
    for (int i = 0; i < 4; i++) {
#pragma unroll
        for (int j = 0; j < 4; j++) {
            int row = m0 + ty * 4 + i;
            int col = n0 + tx * 4 + j;
            float v = acc[i][j] + bias[col];
            if (flags & 2) {
                v = fmaf(gam[col], v * RS, bet[col]);
                v = fmaxf(v, 0.f);
            }
            C[(size_t)row * 256 + col] = v;
        }
    }
}

// ---------------------------------------------------------------------------
// tf32 helpers
// ---------------------------------------------------------------------------
__device__ __forceinline__ uint32_t tf32_of(float x) {
    uint32_t u;
    asm("cvt.rna.tf32.f32 %0, %1;" : "=r"(u) : "f"(x));
    return u;
}

__device__ __forceinline__ void mma_tf32(
    float c[4], uint32_t a0, uint32_t a1, uint32_t a2, uint32_t a3,
    uint32_t b0, uint32_t b1)
{
    asm volatile(
        "mma.sync.aligned.m16n8k8.row.col.f32.tf32.tf32.f32 "
        "{%0,%1,%2,%3}, {%4,%5,%6,%7}, {%8,%9}, {%0,%1,%2,%3};"
        : "+f"(c[0]), "+f"(c[1]), "+f"(c[2]), "+f"(c[3])
        : "r"(a0), "r"(a1), "r"(a2), "r"(a3), "r"(b0), "r"(b1));
}

#define WBUF 4224   // floats per sW buffer (16 p-rows * 264)

// ---------------------------------------------------------------------------
// Chunk GEMM on tensor cores; returns raw fragments c[4][4].
//   - sHz: [32 rows][264] tf32-rounded fp32, paired-k layout:
//       word(row, k) = row*264 + ((k>>3)*4 + (k&3))*2 + ((k&7)>>2)
//   - sW : two buffers of WBUF floats; per 32-k tile,
//       word(kk, r) = p*264 + r*2 + (hi ^ (p>>3)),
//       p=(kk>>3)*4+(kk&3), hi=(kk&7)>>2.
//     The hi-xor flips word-parity for the upper-k half (p>=8), making the
//     32-lane STS conflict-free (even lanes hit even banks, odd lanes odd).
//     Read side: for ks>=2 (p>=8) the LDS.64 pair is (k+4, k) -> swap regs.
// Double-buffered: stage buf[kt&1] -> ONE barrier -> mma from buf[kt&1].
// Register prefetch: next k-tile's 16 weights fetched right after STS.
// ---------------------------------------------------------------------------
__device__ __forceinline__ void gemm_chunk(
    const float* __restrict__ Wg, int r0, int rows,
    const float* __restrict__ sHz, float* __restrict__ sW,
    int tx, int ty, float c[4][4])
{
    const int t   = ty * 32 + tx;
    const int r   = t >> 1;          // weight row within chunk: 0..127
    const int kh  = (t & 1) * 16;    // k-half within 32-k tile
    const int gid = tx >> 2;
    const int tig = tx & 3;
    const int mw  = (ty & 1) * 16;
    const int nw  = (ty >> 1) * 32;

#pragma unroll
    for (int nt = 0; nt < 4; nt++)
#pragma unroll
        for (int j = 0; j < 4; j++) c[nt][j] = 0.f;

    const float* abase = sHz + (mw + gid) * 264 + tig * 2;
    const bool valid = (r < rows);
    const float4* wrow = (const float4*)(Wg + (size_t)(r0 + r) * 256 + kh);

    // prefetch tile kt=0
    float4 v0, v1, v2, v3;
    if (valid) {
        v0 = wrow[0]; v1 = wrow[1]; v2 = wrow[2]; v3 = wrow[3];
    } else {
        v0 = make_float4(0.f, 0.f, 0.f, 0.f);
        v1 = v0; v2 = v0; v3 = v0;
    }

#pragma unroll 2
    for (int kt = 0; kt < 8; kt++) {
        float* buf = sW + (kt & 1) * WBUF;
        float vv[16];
        vv[0]=v0.x; vv[1]=v0.y; vv[2]=v0.z; vv[3]=v0.w;
        vv[4]=v1.x; vv[5]=v1.y; vv[6]=v1.z; vv[7]=v1.w;
        vv[8]=v2.x; vv[9]=v2.y; vv[10]=v2.z; vv[11]=v2.w;
        vv[12]=v3.x; vv[13]=v3.y; vv[14]=v3.z; vv[15]=v3.w;
#pragma unroll
        for (int j = 0; j < 16; j++) {
            int kk = kh + j;
            int p  = ((kk >> 3) << 2) + (kk & 3);
            int hi = (kk & 7) >> 2;
            buf[p * 264 + r * 2 + (hi ^ (p >> 3))] =
                __uint_as_float(tf32_of(vv[j]));
        }
        if (kt < 7 && valid) {     // prefetch next tile (overlaps barrier+mma)
            const float4* src = wrow + (kt + 1) * 8;
            v0 = src[0]; v1 = src[1]; v2 = src[2]; v3 = src[3];
        }
        __syncthreads();           // staging of buf[kt&1] visible to all

        const float* ab = abase + kt * 32;
#pragma unroll
        for (int ks = 0; ks < 4; ks++) {
            float2 al = *(const float2*)(ab + ks * 8);
            float2 ah = *(const float2*)(ab + ks * 8 + 8 * 264);
            uint32_t a0 = __float_as_uint(al.x);
            uint32_t a1 = __float_as_uint(ah.x);
            uint32_t a2 = __float_as_uint(al.y);
            uint32_t a3 = __float_as_uint(ah.y);
            const float* bb = buf + (ks * 4 + tig) * 264 + (nw + gid) * 2;
#pragma unroll
            for (int nt = 0; nt < 4; nt++) {
                float2 bp = *(const float2*)(bb + nt * 16);
                // p = ks*4+tig >= 8 <=> ks >= 2: pair stored swapped
                float b0f = (ks < 2) ? bp.x : bp.y;
                float b1f = (ks < 2) ? bp.y : bp.x;
                mma_tf32(c[nt], a0, a1, a2, a3,
                         __float_as_uint(b0f), __float_as_uint(b1f));
            }
        }
    }
}

// reduce a value over the 4 tig lanes (lane = gid*4 + tig)
__device__ __forceinline__ float red4(float s) {
    s += __shfl_xor_sync(0xffffffffu, s, 1);
    s += __shfl_xor_sync(0xffffffffu, s, 2);
    return s;
}

// Bt chunk: warp quarter = one c index; contract over u, += into sZ[m][c].
__device__ __forceinline__ void bt_epilogue(
    const float c[4][4], const float* __restrict__ bias, int r0,
    const float* __restrict__ sU, float* __restrict__ sZ, int tx, int ty)
{
    const int gid = tx >> 2, tig = tx & 3;
    const int m0r = (ty & 1) * 16 + gid;
    const int nw  = (ty >> 1) * 32;
    const int cidx = (r0 >> 5) + (ty >> 1);
    float s0 = 0.f, s1 = 0.f;
#pragma unroll
    for (int nt = 0; nt < 4; nt++)
#pragma unroll
        for (int e = 0; e < 2; e++) {
            int uu = nt * 8 + tig * 2 + e;           // ncol & 31
            float vb = __ldg(bias + r0 + nw + uu);
            s0 = fmaf(c[nt][e]     + vb, sU[m0r * 32 + uu],       s0);
            s1 = fmaf(c[nt][2 + e] + vb, sU[(m0r + 8) * 32 + uu], s1);
        }
    s0 = red4(s0); s1 = red4(s1);
    if (tig == 0) {
        sZ[m0r * 128 + cidx]       += s0;
        sZ[(m0r + 8) * 128 + cidx] += s1;
    }
}

// Ct chunk (one y per chunk): contract over this warp's 32 c's with sZ,
// combine quarters via smem atomicAdd.
__device__ __forceinline__ void ct_epilogue(
    const float c[4][4], const float* __restrict__ bias, int y,
    const float* __restrict__ sZ, float sign, float* __restrict__ sYt,
    int tx, int ty)
{
    const int gid = tx >> 2, tig = tx & 3;
    const int m0r = (ty & 1) * 16 + gid;
    const int nw  = (ty >> 1) * 32;
    float s0 = 0.f, s1 = 0.f;
#pragma unroll
    for (int nt = 0; nt < 4; nt++)
#pragma unroll
        for (int e = 0; e < 2; e++) {
            int colg = nw + nt * 8 + tig * 2 + e;    // c index 0..127
            float vb = __ldg(bias + y * 128 + colg);
            s0 = fmaf(c[nt][e]     + vb, sZ[m0r * 128 + colg],       s0);
            s1 = fmaf(c[nt][2 + e] + vb, sZ[(m0r + 8) * 128 + colg], s1);
        }
    s0 = red4(s0); s1 = red4(s1);
    if (tig == 0) {
        atomicAdd(&sYt[m0r * 64 + y],       sign * s0);
        atomicAdd(&sYt[(m0r + 8) * 64 + y], sign * s1);
    }
}

// Dt chunk: warp quarter = one y; contract over u, += into sYt[m][y].
__device__ __forceinline__ void dt_epilogue(
    const float c[4][4], const float* __restrict__ bias, int r0, int rows,
    const float* __restrict__ sU, float* __restrict__ sYt, int tx, int ty)
{
    const int nw = (ty >> 1) * 32;
    if (nw >= rows) return;                          // last chunk: 64 rows
    const int gid = tx >> 2, tig = tx & 3;
    const int m0r = (ty & 1) * 16 + gid;
    const int y   = (r0 >> 5) + (ty >> 1);           // <= 49
    float s0 = 0.f, s1 = 0.f;
#pragma unroll
    for (int nt = 0; nt < 4; nt++)
#pragma unroll
        for (int e = 0; e < 2; e++) {
            int uu = nt * 8 + tig * 2 + e;
            float vb = __ldg(bias + r0 + nw + uu);
            s0 = fmaf(c[nt][e]     + vb, sU[m0r * 32 + uu],       s0);
            s1 = fmaf(c[nt][2 + e] + vb, sU[(m0r + 8) * 32 + uu], s1);
        }
    s0 = red4(s0); s1 = red4(s1);
    if (tig == 0) {
        sYt[m0r * 64 + y]       += s0;
        sYt[(m0r + 8) * 64 + y] += s1;
    }
}

// SMEM floats: sHz 8448 | sW 2*4224 | sU 1024 | sZnr 4096 | sZni 4096 | sYt 2048
#define SMEM_FLOATS 28160     // 112640 bytes -> 2 blocks/SM

__global__ __launch_bounds__(256, 2) void fused_heads_kernel(
    const float* __restrict__ zt,   const float* __restrict__ dtv,
    const float* __restrict__ ut,
    const float* __restrict__ aw,   const float* __restrict__ ab,
    const float* __restrict__ ow,   const float* __restrict__ ob,
    const float* __restrict__ btrw, const float* __restrict__ btrb,
    const float* __restrict__ btiw, const float* __restrict__ btib,
    const float* __restrict__ ctrw, const float* __restrict__ ctrb,
    const float* __restrict__ ctiw, const float* __restrict__ ctib,
    const float* __restrict__ dtww, const float* __restrict__ dtwb,
    float* __restrict__ out)
{
    extern __shared__ float sm[];
    float* sHz  = sm;             // [32][264] tf32 paired-k
    float* sW   = sm + 8448;      // [2][4224] weight tile double buffer
    float* sU   = sm + 16896;     // [32][32]  ut*dt
    float* sZnr = sm + 17920;     // [32][128]
    float* sZni = sm + 22016;     // [32][128]
    float* sYt  = sm + 26112;     // [32][64]

    const int t  = threadIdx.x;
    const int tx = t & 31;
    const int ty = t >> 5;
    const int b0 = blockIdx.x * BROWS;

    const int gid = tx >> 2, tig = tx & 3;
    const int m0r = (ty & 1) * 16 + gid;
    const int nw  = (ty >> 1) * 32;

    // phase 0: stage per-tile state (covered by first barrier in gemm_chunk)
    for (int idx = t; idx < BROWS * 256; idx += 256) {
        int row = idx >> 8, k = idx & 255;
        int p  = ((k >> 3) << 2) + (k & 3);
        int hi = (k & 7) >> 2;
        sHz[row * 264 + p * 2 + hi] =
            __uint_as_float(tf32_of(g_hz[(size_t)b0 * 256 + idx]));
    }
    for (int idx = t; idx < BROWS * 32; idx += 256) {
        int br = idx >> 5;
        sU[idx] = ut[(size_t)(b0 + br) * 32 + (idx & 31)] * dtv[b0 + br];
    }
    for (int idx = t; idx < BROWS * 64; idx += 256) sYt[idx] = 0.f;

    float c[4][4], ea[4][4];

    // alpha -> exp(-softplus(v)) == sigmoid(-v); fragment-native
    gemm_chunk(aw, 0, 128, sHz, sW, tx, ty, c);
#pragma unroll
    for (int nt = 0; nt < 4; nt++)
#pragma unroll
        for (int j = 0; j < 4; j++) {
            int colg = nw + nt * 8 + tig * 2 + (j & 1);
            float v = c[nt][j] + __ldg(ab + colg);
            ea[nt][j] = 1.0f / (1.0f + expf(v));
        }

    // omega -> Lam = ea*(cos,sin); init z_next = Lam * z; direct stores
    gemm_chunk(ow, 0, 128, sHz, sW, tx, ty, c);
#pragma unroll
    for (int nt = 0; nt < 4; nt++)
#pragma unroll
        for (int j = 0; j < 4; j++) {
            int colg = nw + nt * 8 + tig * 2 + (j & 1);
            int m    = m0r + ((j >> 1) ? 8 : 0);
            float v = c[nt][j] + __ldg(ob + colg);
            float sn, cs;
            sincosf(v, &sn, &cs);
            float lr = ea[nt][j] * cs;
            float li = ea[nt][j] * sn;
            int b = b0 + m;
            float zr = __ldg(zt + (size_t)b * 256 + colg);
            float zi = __ldg(zt + (size_t)b * 256 + 128 + colg);
            sZnr[m * 128 + colg] = lr * zr - li * zi;
            sZni[m * 128 + colg] = lr * zi + li * zr;
        }

    // Bt real / imag: 32 chunks each (4096 rows / 128)
    for (int ch = 0; ch < 32; ch++) {
        gemm_chunk(btrw, ch * 128, 128, sHz, sW, tx, ty, c);
        bt_epilogue(c, btrb, ch * 128, sU, sZnr, tx, ty);
    }
    for (int ch = 0; ch < 32; ch++) {
        gemm_chunk(btiw, ch * 128, 128, sHz, sW, tx, ty, c);
        bt_epilogue(c, btib, ch * 128, sU, sZni, tx, ty);
    }

    // Ct real / imag: 50 chunks each (one y per 128-row chunk)
    for (int y = 0; y < NY; y++) {
        gemm_chunk(ctrw, y * 128, 128, sHz, sW, tx, ty, c);
        ct_epilogue(c, ctrb, y, sZnr, 1.f, sYt, tx, ty);
    }
    for (int y = 0; y < NY; y++) {
        gemm_chunk(ctiw, y * 128, 128, sHz, sW, tx, ty, c);
        ct_epilogue(c, ctib, y, sZni, -1.f, sYt, tx, ty);
    }

    // Dt: 1600 rows = 12 full chunks + 64
    for (int ch = 0; ch < 13; ch++) {
        int rows = (ch == 12) ? 64 : 128;
        gemm_chunk(dtww, ch * 128, rows, sHz, sW, tx, ty, c);
        dt_epilogue(c, dtwb, ch * 128, rows, sU, sYt, tx, ty);
    }

    __syncthreads();

    // outputs: z_next_real [B,256] then yt [B,50]
    for (int idx = t; idx < BROWS * 256; idx += 256) {
        int br = idx >> 8;
        int j  = idx & 255;
        float v = (j < 128) ? sZnr[br * 128 + j] : sZni[br * 128 + j - 128];
        out[(size_t)(b0 + br) * 256 + j] = v;
    }
    for (int idx = t; idx < BROWS * NY; idx += 256) {
        int br = idx / NY;
        int y  = idx % NY;
        out[(size_t)BATCH * 256 + (size_t)(b0 + br) * NY + y] = sYt[br * 64 + y];
    }
}

// ---------------------------------------------------------------------------
extern "C" void kernel_launch(void* const* d_in, const int* in_sizes, int n_in,
                              void* d_out, int out_size)
{
    const float* zt   = (const float*)d_in[0];
    const float* dtv  = (const float*)d_in[1];
    const float* ut   = (const float*)d_in[2];
    const float* sw0  = (const float*)d_in[3];
    const float* sb0  = (const float*)d_in[4];
    const float* sg0  = (const float*)d_in[5];
    const float* sbe0 = (const float*)d_in[6];
    const float* sw1  = (const float*)d_in[7];
    const float* sb1  = (const float*)d_in[8];
    const float* sg1  = (const float*)d_in[9];
    const float* sbe1 = (const float*)d_in[10];
    const float* sw2  = (const float*)d_in[11];
    const float* sb2  = (const float*)d_in[12];
    const float* aw   = (const float*)d_in[13];
    const float* ab   = (const float*)d_in[14];
    const float* ow   = (const float*)d_in[15];
    const float* ob   = (const float*)d_in[16];
    const float* btrw = (const float*)d_in[17];
    const float* btrb = (const float*)d_in[18];
    const float* btiw = (const float*)d_in[19];
    const float* btib = (const float*)d_in[20];
    const float* ctrw = (const float*)d_in[21];
    const float* ctrb = (const float*)d_in[22];
    const float* ctiw = (const float*)d_in[23];
    const float* ctib = (const float*)d_in[24];
    const float* dtww = (const float*)d_in[25];
    const float* dtwb = (const float*)d_in[26];

    float *p0, *p1, *phz;
    cudaGetSymbolAddress((void**)&p0,  g_buf0);
    cudaGetSymbolAddress((void**)&p1,  g_buf1);
    cudaGetSymbolAddress((void**)&phz, g_hz);

    dim3 gsel(BATCH / 64, 256 / 64);
    // layer0: concat input, BN+ReLU
    sel_gemm_kernel<<<gsel, 256>>>(nullptr, zt, ut, dtv,
                                   sw0, sb0, sg0, sbe0, p0, SELIN, 3);
    // layer1: BN+ReLU
    sel_gemm_kernel<<<gsel, 256>>>(p0, nullptr, nullptr, nullptr,
                                   sw1, sb1, sg1, sbe1, p1, 256, 2);
    // layer2: plain linear -> hz
    sel_gemm_kernel<<<gsel, 256>>>(p1, nullptr, nullptr, nullptr,
                                   sw2, sb2, nullptr, nullptr, phz, 256, 0);

    const int smem_bytes = SMEM_FLOATS * (int)sizeof(float);  // 112640
    cudaFuncSetAttribute(fused_heads_kernel,
                         cudaFuncAttributeMaxDynamicSharedMemorySize, smem_bytes);
    fused_heads_kernel<<<BATCH / BROWS, 256, smem_bytes>>>(
        zt, dtv, ut,
        aw, ab, ow, ob,
        btrw, btrb, btiw, btib,
        ctrw, ctrb, ctiw, ctib,
        dtww, dtwb,
        (float*)d_out);
}